// round 11
// baseline (speedup 1.0000x reference)
#include <cuda_runtime.h>
#include <cstdint>

#define W129 129
#define NPIX (129*129)
#define PW   131
#define PADROWS 17792
#define MT128 133          // ceil(16899/128) M-tiles of 128

// ---------------- scratch (device globals) ----------------------------------
__device__ float g_ups[4u*PADROWS*128];     // [img][padpos][128] NHWC, tf32 vals
__device__ float g_ccat[2u*PADROWS*512];    // [b][padpos][512]   NHWC, tf32 vals
__device__ float g_wtr[9*256*128];          // [rs][oc][ic] tf32
__device__ float g_wt2[9*256*512];          // [rs][oc][ic] tf32
__device__ float g_y[2u*NPIX*256];          // [img][pix][256] fp32 NHWC
__device__ float g_ker[2*49*NPIX];          // [img][o][pix]

// ========================= helpers ==========================================
__device__ __forceinline__ float tf32r(float x) {
    asm("cvt.rna.tf32.f32 %0, %0;" : "+f"(x));
    return x;
}
__device__ __forceinline__ uint32_t smem_u32(const void* p) {
    uint32_t a;
    asm("{ .reg .u64 t; cvta.to.shared.u64 t, %1; cvt.u32.u64 %0, t; }" : "=r"(a) : "l"(p));
    return a;
}
__device__ __forceinline__ void cp_async16(uint32_t dst, const void* src) {
    asm volatile("cp.async.cg.shared.global [%0], [%1], 16;" :: "r"(dst), "l"(src) : "memory");
}
__device__ __forceinline__ void cp_commit() {
    asm volatile("cp.async.commit_group;" ::: "memory");
}
__device__ __forceinline__ void mma_tf32_16x8x8(float* c, const uint32_t* a, const uint32_t* b) {
    asm volatile(
        "mma.sync.aligned.m16n8k8.row.col.f32.tf32.tf32.f32 "
        "{%0,%1,%2,%3}, {%4,%5,%6,%7}, {%8,%9}, {%0,%1,%2,%3};"
        : "+f"(c[0]), "+f"(c[1]), "+f"(c[2]), "+f"(c[3])
        : "r"(a[0]), "r"(a[1]), "r"(a[2]), "r"(a[3]), "r"(b[0]), "r"(b[1]));
}

// ========================= aux kernels ======================================
__global__ void zero_kernel(float4* a, size_t na, float4* b, size_t nb) {
    size_t i = (size_t)blockIdx.x * blockDim.x + threadIdx.x;
    size_t stride = (size_t)gridDim.x * blockDim.x;
    float4 z = make_float4(0.f, 0.f, 0.f, 0.f);
    for (size_t k = i; k < na; k += stride) a[k] = z;
    for (size_t k = i; k < nb; k += stride) b[k] = z;
}

__global__ void transpose_w_tf32(const float* __restrict__ src,
                                 float* __restrict__ dst, int IC) {
    int idx = blockIdx.x * blockDim.x + threadIdx.x;
    int total = 9 * 256 * IC;
    if (idx >= total) return;
    int ic = idx % IC;
    int oc = (idx / IC) % 256;
    int rs = idx / (IC * 256);
    dst[idx] = tf32r(src[((size_t)oc * IC + ic) * 9 + rs]);
}

__global__ __launch_bounds__(256) void upsample_nhwc(const float* __restrict__ cur,
                                                     const float* __restrict__ key,
                                                     float* __restrict__ ups) {
    __shared__ float s[128][2][33];
    int y = blockIdx.x;          // 0..128
    int img = blockIdx.y;        // 0..3
    int b = img >> 1, frame = img & 1;
    const float* src = (frame ? key : cur) + (size_t)b * 128 * 1089;
    const float scale = 33.0f / 129.0f;
    float sy = fminf(fmaxf((y + 0.5f) * scale - 0.5f, 0.0f), 32.0f);
    int y0 = (int)sy, y1 = min(y0 + 1, 32);
    float fy = sy - (float)y0;
    for (int idx = threadIdx.x; idx < 128 * 66; idx += 256) {
        int c = idx / 66, rem = idx % 66;
        int yy = rem / 33, x = rem % 33;
        s[c][yy][x] = src[c * 1089 + (yy ? y1 : y0) * 33 + x];
    }
    __syncthreads();
    float* dst = ups + ((size_t)img * PADROWS + (size_t)(y + 1) * PW + 1) * 128;
    for (int e = threadIdx.x; e < 129 * 128; e += 256) {
        int x = e >> 7, c = e & 127;
        float sx = fminf(fmaxf((x + 0.5f) * scale - 0.5f, 0.0f), 32.0f);
        int x0 = (int)sx, x1 = min(x0 + 1, 32);
        float fx = sx - (float)x0;
        float v0 = s[c][0][x0] + (s[c][0][x1] - s[c][0][x0]) * fx;
        float v1 = s[c][1][x0] + (s[c][1][x1] - s[c][1][x0]) * fx;
        dst[(size_t)x * 128 + c] = tf32r(v0 + (v1 - v0) * fy);
    }
}

// ============== warp-MMA tf32 implicit-GEMM 3x3 conv ========================
// CTA: M=128 padded-grid positions x N=256 oc (ALL output channels).
// 512 threads / 16 warps, each warp 64x32. 3-stage cp.async pipeline.
// smem stage: A 128x36 + B 256x36 floats (stride-36 pad -> conflict-free)
#define SK 36
#define STAGEFLOATS ((128 + 256) * SK)           // 13824
#define STAGEBYTES  (STAGEFLOATS * 4)            // 55296

template<int IC, bool TO_CCAT>
__global__ __launch_bounds__(512, 1)
void conv_mma_kernel(const float* __restrict__ in,
                     const float* __restrict__ wt,
                     const float* __restrict__ bias,
                     float* __restrict__ outbuf) {
    extern __shared__ float dsm[];

    const int tid = threadIdx.x;
    const int wid = tid >> 5;
    const int lane = tid & 31;
    const int r = lane >> 2;         // 0..7
    const int cth = lane & 3;        // 0..3

    const int q0 = blockIdx.x * 128;
    const int img = blockIdx.y;
    const int wm = wid & 1;          // m-half (64)
    const int wn = wid >> 1;         // n-block of 32 (0..7)

    const float* in_img = in + (size_t)img * PADROWS * IC;
    const uint32_t smem0 = smem_u32(dsm);

    const int KC = IC / 32;          // ic-chunks per tap
    const int NK = 9 * KC;

    float c[4][4][4];
#pragma unroll
    for (int mt = 0; mt < 4; mt++)
#pragma unroll
        for (int nt = 0; nt < 4; nt++)
#pragma unroll
            for (int v = 0; v < 4; v++) c[mt][nt][v] = 0.0f;

    const int l_row = tid >> 3;      // 0..63
    const int l_k4  = tid & 7;       // float4 index within 32 floats

    // ---- chunk loader: A 128 rows, B 256 rows, 32 ic floats each ----
    auto issue_chunk = [&](int ch, int buf) {
        int rs = ch / KC, icc = ch % KC;
        int dq = (rs / 3) * PW + (rs % 3);
        int ic0 = icc * 32;
        uint32_t As = smem0 + buf * STAGEBYTES;
        uint32_t Bs = As + 128 * SK * 4;
        const float* gA = in_img + (size_t)(q0 + dq) * IC + ic0;
        const float* gB = wt + (size_t)rs * 256 * IC + ic0;
#pragma unroll
        for (int i = 0; i < 2; i++) {          // A: 128 rows
            int row = l_row + i * 64;
            cp_async16(As + row * (SK * 4) + l_k4 * 16, gA + (size_t)row * IC + l_k4 * 4);
        }
#pragma unroll
        for (int i = 0; i < 4; i++) {          // B: 256 rows
            int row = l_row + i * 64;
            cp_async16(Bs + row * (SK * 4) + l_k4 * 16, gB + (size_t)row * IC + l_k4 * 4);
        }
        cp_commit();
    };

    issue_chunk(0, 0);
    issue_chunk(1, 1);

    for (int j = 0; j < NK; j++) {
        __syncthreads();             // all warps done computing chunk j-1 (buf (j+2)%3)
        if (j + 2 < NK) issue_chunk(j + 2, (j + 2) % 3);
        int pend = NK - 1 - j;
        if (pend >= 2)      asm volatile("cp.async.wait_group 2;" ::: "memory");
        else if (pend == 1) asm volatile("cp.async.wait_group 1;" ::: "memory");
        else                asm volatile("cp.async.wait_group 0;" ::: "memory");
        __syncthreads();

        const float* sAf = dsm + (j % 3) * STAGEFLOATS;
        const float* sBf = sAf + 128 * SK;
        const float* apb = sAf + (wm * 64 + r) * SK + cth;
        const float* bpb = sBf + (wn * 32 + r) * SK + cth;
#pragma unroll
        for (int ks = 0; ks < 4; ks++) {
            int k0 = ks * 8;
            uint32_t a[4][4], b[4][2];
#pragma unroll
            for (int mt = 0; mt < 4; mt++) {
                const float* ap = apb + mt * 16 * SK + k0;
                a[mt][0] = __float_as_uint(ap[0]);
                a[mt][1] = __float_as_uint(ap[8 * SK]);
                a[mt][2] = __float_as_uint(ap[4]);
                a[mt][3] = __float_as_uint(ap[8 * SK + 4]);
            }
#pragma unroll
            for (int nt = 0; nt < 4; nt++) {
                const float* bp = bpb + nt * 8 * SK + k0;
                b[nt][0] = __float_as_uint(bp[0]);
                b[nt][1] = __float_as_uint(bp[4]);
            }
#pragma unroll
            for (int mt = 0; mt < 4; mt++)
#pragma unroll
                for (int nt = 0; nt < 4; nt++)
                    mma_tf32_16x8x8(c[mt][nt], a[mt], b[nt]);
        }
    }

    // ---- epilogue: bias + relu, scatter to NHWC ----
#pragma unroll
    for (int nt = 0; nt < 4; nt++) {
        int nglob = wn * 32 + nt * 8 + cth * 2;
        float b0 = __ldg(bias + nglob);
        float b1 = __ldg(bias + nglob + 1);
#pragma unroll
        for (int mt = 0; mt < 4; mt++) {
#pragma unroll
            for (int half = 0; half < 2; half++) {
                int q = q0 + wm * 64 + mt * 16 + r + half * 8;
                int Y = q / PW, X = q - Y * PW;
                if (X < 129 && Y < 129) {
                    float v0 = fmaxf(c[mt][nt][half * 2 + 0] + b0, 0.0f);
                    float v1 = fmaxf(c[mt][nt][half * 2 + 1] + b1, 0.0f);
                    float* dst;
                    if (TO_CCAT) {
                        v0 = tf32r(v0); v1 = tf32r(v1);
                        dst = outbuf + ((size_t)(img >> 1) * PADROWS
                              + (size_t)(Y + 1) * PW + (X + 1)) * 512
                              + (img & 1) * 256 + nglob;
                    } else {
                        dst = outbuf + ((size_t)img * NPIX + (size_t)Y * W129 + X) * 256 + nglob;
                    }
                    *reinterpret_cast<float2*>(dst) = make_float2(v0, v1);
                }
            }
        }
    }
}

// -------- 1x1 conv (NHWC input) + bias + relu + softmax ---------------------
__global__ __launch_bounds__(256) void conv1x1_softmax_nhwc(
        const float* __restrict__ yb, const float* __restrict__ w,
        const float* __restrict__ bias, float* __restrict__ ker) {
    __shared__ float s_w[49 * 128];
    const int img = blockIdx.y;
    int p = blockIdx.x * 256 + threadIdx.x;
    const bool valid = p < NPIX;
    int pc = valid ? p : NPIX - 1;
    const float* xr = yb + ((size_t)img * NPIX + pc) * 256;

    float acc[49];
#pragma unroll
    for (int o = 0; o < 49; o++) acc[o] = 0.0f;

    for (int ic0 = 0; ic0 < 256; ic0 += 128) {
        __syncthreads();
        for (int idx = threadIdx.x; idx < 49 * 128; idx += 256) {
            int o = idx >> 7, i = idx & 127;
            s_w[idx] = w[o * 256 + ic0 + i];
        }
        __syncthreads();
#pragma unroll 2
        for (int i = 0; i < 128; i += 4) {
            float4 x4 = *reinterpret_cast<const float4*>(xr + ic0 + i);
#pragma unroll
            for (int o = 0; o < 49; o++) {
                const float* wp = &s_w[o * 128 + i];
                acc[o] += x4.x * wp[0] + x4.y * wp[1] + x4.z * wp[2] + x4.w * wp[3];
            }
        }
    }
    float m = -1e30f;
#pragma unroll
    for (int o = 0; o < 49; o++) {
        acc[o] = fmaxf(acc[o] + bias[o], 0.0f);
        m = fmaxf(m, acc[o]);
    }
    float sum = 0.0f;
#pragma unroll
    for (int o = 0; o < 49; o++) {
        acc[o] = expf(acc[o] - m);
        sum += acc[o];
    }
    float inv = 1.0f / sum;
    if (valid) {
        float* k_img = ker + (size_t)img * 49 * NPIX;
#pragma unroll
        for (int o = 0; o < 49; o++)
            k_img[(size_t)o * NPIX + p] = acc[o] * inv;
    }
}

// -------- spatially-variant 7x7 conv (unchanged, passing) -------------------
__global__ __launch_bounds__(256) void svconv_kernel(const float* __restrict__ f,
                              const float* __restrict__ ker,
                              float* __restrict__ out) {
    __shared__ float s_f[8][22][22];
    const int tx = threadIdx.x & 15, ty = threadIdx.x >> 4;
    const int col0 = blockIdx.x * 16, row0 = blockIdx.y * 16;
    const int z = blockIdx.z;
    const int c_base = (z & 3) * 64;
    const int img = z >> 2;

    const int gy = row0 + ty, gx = col0 + tx;
    const bool valid = (gy < 129) && (gx < 129);
    const float* f_img = f   + (size_t)img * 256 * NPIX;
    const float* k_img = ker + (size_t)img * 49  * NPIX;
    float*       o_img = out + (size_t)img * 256 * NPIX;

    float kv[49];
    int pclamp = valid ? gy * W129 + gx : 0;
#pragma unroll
    for (int o = 0; o < 49; o++) kv[o] = k_img[(size_t)o * NPIX + pclamp];

    for (int cc = 0; cc < 64; cc += 8) {
        __syncthreads();
        for (int idx = threadIdx.x; idx < 8 * 22 * 22; idx += 256) {
            int cx = idx % 22;
            int cy = (idx / 22) % 22;
            int ch = idx / 484;
            int gr = row0 - 3 + cy, gc = col0 - 3 + cx;
            float v = 0.0f;
            if ((unsigned)gr < 129u && (unsigned)gc < 129u)
                v = f_img[(size_t)(c_base + cc + ch) * NPIX + gr * W129 + gc];
            s_f[ch][cy][cx] = v;
        }
        __syncthreads();
#pragma unroll 1
        for (int ch = 0; ch < 8; ch++) {
            float acc = 0.0f;
#pragma unroll
            for (int i = 0; i < 7; i++)
#pragma unroll
                for (int j = 0; j < 7; j++)
                    acc += kv[i * 7 + j] * s_f[ch][ty + i][tx + j];
            if (valid)
                o_img[(size_t)(c_base + cc + ch) * NPIX + gy * W129 + gx] = acc;
        }
    }
}

// ========================= launch ============================================
extern "C" void kernel_launch(void* const* d_in, const int* in_sizes, int n_in,
                              void* d_out, int out_size) {
    const float* cur      = (const float*)d_in[0];
    const float* key      = (const float*)d_in[1];
    const float* high     = (const float*)d_in[2];
    const float* w_reduce = (const float*)d_in[3];
    const float* b_reduce = (const float*)d_in[4];
    const float* w_conv2  = (const float*)d_in[5];
    const float* b_conv2  = (const float*)d_in[6];
    const float* w_conv3  = (const float*)d_in[7];
    const float* b_conv3  = (const float*)d_in[8];
    float* out = (float*)d_out;

    float *ups, *ccat, *wtr, *wt2, *yb, *kb;
    cudaGetSymbolAddress((void**)&ups,  g_ups);
    cudaGetSymbolAddress((void**)&ccat, g_ccat);
    cudaGetSymbolAddress((void**)&wtr,  g_wtr);
    cudaGetSymbolAddress((void**)&wt2,  g_wt2);
    cudaGetSymbolAddress((void**)&yb,   g_y);
    cudaGetSymbolAddress((void**)&kb,   g_ker);

    const int SMEM_DYN = 3 * STAGEBYTES;   // 165888
    cudaFuncSetAttribute(conv_mma_kernel<128, true>,
                         cudaFuncAttributeMaxDynamicSharedMemorySize, SMEM_DYN);
    cudaFuncSetAttribute(conv_mma_kernel<512, false>,
                         cudaFuncAttributeMaxDynamicSharedMemorySize, SMEM_DYN);

    // 1. zero padded NHWC buffers (halos + garbage tail must read 0)
    zero_kernel<<<2048, 256>>>((float4*)ups,  (size_t)4 * PADROWS * 128 / 4,
                               (float4*)ccat, (size_t)2 * PADROWS * 512 / 4);
    // 2. weights -> [rs][oc][ic], tf32
    {
        int t1 = 9 * 256 * 128;
        transpose_w_tf32<<<(t1 + 255) / 256, 256>>>(w_reduce, wtr, 128);
        int t2 = 9 * 256 * 512;
        transpose_w_tf32<<<(t2 + 255) / 256, 256>>>(w_conv2, wt2, 512);
    }
    // 3. bilinear upsample -> NHWC padded, tf32
    {
        dim3 grid(129, 4);
        upsample_nhwc<<<grid, 256>>>(cur, key, ups);
    }
    // 4. conv_reduce: 4 imgs, IC=128 -> ccat (NHWC padded, tf32)
    {
        dim3 grid(MT128, 4);
        conv_mma_kernel<128, true><<<grid, 512, SMEM_DYN>>>(ups, wtr, b_reduce, ccat);
    }
    // 5. conv2: 2 imgs, IC=512 -> y (NHWC, fp32)
    {
        dim3 grid(MT128, 2);
        conv_mma_kernel<512, false><<<grid, 512, SMEM_DYN>>>(ccat, wt2, b_conv2, yb);
    }
    // 6. 1x1 conv + softmax -> kernels
    {
        dim3 grid((NPIX + 255) / 256, 2);
        conv1x1_softmax_nhwc<<<grid, 256>>>(yb, w_conv3, b_conv3, kb);
    }
    // 7. spatially-variant 7x7 conv -> output
    {
        dim3 grid(9, 9, 8);
        svconv_kernel<<<grid, 256>>>(high, kb, out);
    }
}

// round 12
// speedup vs baseline: 1.0581x; 1.0581x over previous
#include <cuda_runtime.h>
#include <cstdint>

#define W129 129
#define NPIX (129*129)
#define PW   131
#define PADROWS 17792
#define MT128 133          // ceil(16899/128) M-tiles of 128

// ---------------- scratch (device globals) ----------------------------------
__device__ float g_ups[4u*PADROWS*128];     // [img][padpos][128] NHWC, tf32 vals
__device__ float g_ccat[2u*PADROWS*512];    // [b][padpos][512]   NHWC, tf32 vals
__device__ float g_wtr[9*256*128];          // [rs][oc][ic] tf32
__device__ float g_wt2[9*256*512];          // [rs][oc][ic] tf32
__device__ float g_y[2u*NPIX*256];          // [img][pix][256] fp32 NHWC
__device__ float g_ker[2*49*NPIX];          // [img][o][pix]

// ========================= helpers ==========================================
__device__ __forceinline__ float tf32r(float x) {
    asm("cvt.rna.tf32.f32 %0, %0;" : "+f"(x));
    return x;
}
__device__ __forceinline__ uint32_t smem_u32(const void* p) {
    uint32_t a;
    asm("{ .reg .u64 t; cvta.to.shared.u64 t, %1; cvt.u32.u64 %0, t; }" : "=r"(a) : "l"(p));
    return a;
}
__device__ __forceinline__ void cp_async16(uint32_t dst, const void* src) {
    asm volatile("cp.async.cg.shared.global [%0], [%1], 16;" :: "r"(dst), "l"(src) : "memory");
}
__device__ __forceinline__ void cp_commit() {
    asm volatile("cp.async.commit_group;" ::: "memory");
}
__device__ __forceinline__ void mma_tf32_16x8x8(float* c, const uint32_t* a, const uint32_t* b) {
    asm volatile(
        "mma.sync.aligned.m16n8k8.row.col.f32.tf32.tf32.f32 "
        "{%0,%1,%2,%3}, {%4,%5,%6,%7}, {%8,%9}, {%0,%1,%2,%3};"
        : "+f"(c[0]), "+f"(c[1]), "+f"(c[2]), "+f"(c[3])
        : "r"(a[0]), "r"(a[1]), "r"(a[2]), "r"(a[3]), "r"(b[0]), "r"(b[1]));
}

// ========================= aux kernels ======================================
__global__ void zero_kernel(float4* a, size_t na, float4* b, size_t nb) {
    size_t i = (size_t)blockIdx.x * blockDim.x + threadIdx.x;
    size_t stride = (size_t)gridDim.x * blockDim.x;
    float4 z = make_float4(0.f, 0.f, 0.f, 0.f);
    for (size_t k = i; k < na; k += stride) a[k] = z;
    for (size_t k = i; k < nb; k += stride) b[k] = z;
}

__global__ void transpose_w_tf32(const float* __restrict__ src,
                                 float* __restrict__ dst, int IC) {
    int idx = blockIdx.x * blockDim.x + threadIdx.x;
    int total = 9 * 256 * IC;
    if (idx >= total) return;
    int ic = idx % IC;
    int oc = (idx / IC) % 256;
    int rs = idx / (IC * 256);
    dst[idx] = tf32r(src[((size_t)oc * IC + ic) * 9 + rs]);
}

__global__ __launch_bounds__(256) void upsample_nhwc(const float* __restrict__ cur,
                                                     const float* __restrict__ key,
                                                     float* __restrict__ ups) {
    __shared__ float s[128][2][33];
    int y = blockIdx.x;          // 0..128
    int img = blockIdx.y;        // 0..3
    int b = img >> 1, frame = img & 1;
    const float* src = (frame ? key : cur) + (size_t)b * 128 * 1089;
    const float scale = 33.0f / 129.0f;
    float sy = fminf(fmaxf((y + 0.5f) * scale - 0.5f, 0.0f), 32.0f);
    int y0 = (int)sy, y1 = min(y0 + 1, 32);
    float fy = sy - (float)y0;
    for (int idx = threadIdx.x; idx < 128 * 66; idx += 256) {
        int c = idx / 66, rem = idx % 66;
        int yy = rem / 33, x = rem % 33;
        s[c][yy][x] = src[c * 1089 + (yy ? y1 : y0) * 33 + x];
    }
    __syncthreads();
    float* dst = ups + ((size_t)img * PADROWS + (size_t)(y + 1) * PW + 1) * 128;
    for (int e = threadIdx.x; e < 129 * 128; e += 256) {
        int x = e >> 7, c = e & 127;
        float sx = fminf(fmaxf((x + 0.5f) * scale - 0.5f, 0.0f), 32.0f);
        int x0 = (int)sx, x1 = min(x0 + 1, 32);
        float fx = sx - (float)x0;
        float v0 = s[c][0][x0] + (s[c][0][x1] - s[c][0][x0]) * fx;
        float v1 = s[c][1][x0] + (s[c][1][x1] - s[c][1][x0]) * fx;
        dst[(size_t)x * 128 + c] = tf32r(v0 + (v1 - v0) * fy);
    }
}

// ============== warp-MMA tf32 implicit-GEMM 3x3 conv ========================
// CTA: M=128 padded-grid positions x N=128 oc. 8 warps, each 64x32.
// K-chunks of 32 ic per tap; THREE-stage cp.async pipeline (2 CTAs/SM).
// smem per stage: A 128x36 + B 128x36 floats (stride-36 pad -> conflict-free)
#define SK 36
#define STAGEFLOATS (2 * 128 * SK)            // 9216
#define STAGEBYTES  (STAGEFLOATS * 4)         // 36864

template<int IC, bool TO_CCAT>
__global__ __launch_bounds__(256, 2)
void conv_mma_kernel(const float* __restrict__ in,
                     const float* __restrict__ wt,
                     const float* __restrict__ bias,
                     float* __restrict__ outbuf) {
    extern __shared__ float dsm[];

    const int tid = threadIdx.x;
    const int wid = tid >> 5;
    const int lane = tid & 31;
    const int r = lane >> 2;         // 0..7
    const int cth = lane & 3;        // 0..3

    const int q0 = blockIdx.x * 128;
    const int img = blockIdx.y;
    const int ocbase = blockIdx.z * 128;
    const int wm = wid & 1;          // m-half (64)
    const int wn = wid >> 1;         // n-quarter (32)

    const float* in_img = in + (size_t)img * PADROWS * IC;
    const uint32_t smem0 = smem_u32(dsm);

    const int KC = IC / 32;          // ic-chunks per tap
    const int NK = 9 * KC;

    float c[4][4][4];
#pragma unroll
    for (int mt = 0; mt < 4; mt++)
#pragma unroll
        for (int nt = 0; nt < 4; nt++)
#pragma unroll
            for (int v = 0; v < 4; v++) c[mt][nt][v] = 0.0f;

    const int l_row = tid >> 3;      // 0..31
    const int l_k4  = tid & 7;       // float4 index within 32 floats

    // ---- chunk loader ----
    auto issue_chunk = [&](int ch, int buf) {
        int rs = ch / KC, icc = ch % KC;
        int dq = (rs / 3) * PW + (rs % 3);
        int ic0 = icc * 32;
        uint32_t As = smem0 + buf * STAGEBYTES;
        uint32_t Bs = As + 128 * SK * 4;
        const float* gA = in_img + (size_t)(q0 + dq) * IC + ic0;
        const float* gB = wt + ((size_t)rs * 256 + ocbase) * IC + ic0;
#pragma unroll
        for (int i = 0; i < 4; i++) {
            int row = l_row + i * 32;
            cp_async16(As + row * (SK * 4) + l_k4 * 16, gA + (size_t)row * IC + l_k4 * 4);
        }
#pragma unroll
        for (int i = 0; i < 4; i++) {
            int row = l_row + i * 32;
            cp_async16(Bs + row * (SK * 4) + l_k4 * 16, gB + (size_t)row * IC + l_k4 * 4);
        }
        cp_commit();
    };

    issue_chunk(0, 0);
    issue_chunk(1, 1);

    for (int j = 0; j < NK; j++) {
        __syncthreads();             // readers from iter j-1 are done with buf (j+2)%3
        if (j + 2 < NK) issue_chunk(j + 2, (j + 2) % 3);
        int pend = NK - 1 - j;
        if (pend >= 2)      asm volatile("cp.async.wait_group 2;" ::: "memory");
        else if (pend == 1) asm volatile("cp.async.wait_group 1;" ::: "memory");
        else                asm volatile("cp.async.wait_group 0;" ::: "memory");
        __syncthreads();

        const float* sAf = dsm + (j % 3) * STAGEFLOATS;
        const float* sBf = sAf + 128 * SK;
        const float* apb = sAf + (wm * 64 + r) * SK + cth;
        const float* bpb = sBf + (wn * 32 + r) * SK + cth;
#pragma unroll
        for (int ks = 0; ks < 4; ks++) {
            int k0 = ks * 8;
            uint32_t a[4][4], b[4][2];
#pragma unroll
            for (int mt = 0; mt < 4; mt++) {
                const float* ap = apb + mt * 16 * SK + k0;
                a[mt][0] = __float_as_uint(ap[0]);
                a[mt][1] = __float_as_uint(ap[8 * SK]);
                a[mt][2] = __float_as_uint(ap[4]);
                a[mt][3] = __float_as_uint(ap[8 * SK + 4]);
            }
#pragma unroll
            for (int nt = 0; nt < 4; nt++) {
                const float* bp = bpb + nt * 8 * SK + k0;
                b[nt][0] = __float_as_uint(bp[0]);
                b[nt][1] = __float_as_uint(bp[4]);
            }
#pragma unroll
            for (int mt = 0; mt < 4; mt++)
#pragma unroll
                for (int nt = 0; nt < 4; nt++)
                    mma_tf32_16x8x8(c[mt][nt], a[mt], b[nt]);
        }
    }

    // ---- epilogue: bias + relu, scatter to NHWC ----
#pragma unroll
    for (int nt = 0; nt < 4; nt++) {
        int nglob = ocbase + wn * 32 + nt * 8 + cth * 2;
        float b0 = __ldg(bias + nglob);
        float b1 = __ldg(bias + nglob + 1);
#pragma unroll
        for (int mt = 0; mt < 4; mt++) {
#pragma unroll
            for (int half = 0; half < 2; half++) {
                int q = q0 + wm * 64 + mt * 16 + r + half * 8;
                int Y = q / PW, X = q - Y * PW;
                if (X < 129 && Y < 129) {
                    float v0 = fmaxf(c[mt][nt][half * 2 + 0] + b0, 0.0f);
                    float v1 = fmaxf(c[mt][nt][half * 2 + 1] + b1, 0.0f);
                    float* dst;
                    if (TO_CCAT) {
                        v0 = tf32r(v0); v1 = tf32r(v1);
                        dst = outbuf + ((size_t)(img >> 1) * PADROWS
                              + (size_t)(Y + 1) * PW + (X + 1)) * 512
                              + (img & 1) * 256 + nglob;
                    } else {
                        dst = outbuf + ((size_t)img * NPIX + (size_t)Y * W129 + X) * 256 + nglob;
                    }
                    *reinterpret_cast<float2*>(dst) = make_float2(v0, v1);
                }
            }
        }
    }
}

// -------- 1x1 conv (NHWC input) + bias + relu + softmax ---------------------
__global__ __launch_bounds__(256) void conv1x1_softmax_nhwc(
        const float* __restrict__ yb, const float* __restrict__ w,
        const float* __restrict__ bias, float* __restrict__ ker) {
    __shared__ float s_w[49 * 128];
    const int img = blockIdx.y;
    int p = blockIdx.x * 256 + threadIdx.x;
    const bool valid = p < NPIX;
    int pc = valid ? p : NPIX - 1;
    const float* xr = yb + ((size_t)img * NPIX + pc) * 256;

    float acc[49];
#pragma unroll
    for (int o = 0; o < 49; o++) acc[o] = 0.0f;

    for (int ic0 = 0; ic0 < 256; ic0 += 128) {
        __syncthreads();
        for (int idx = threadIdx.x; idx < 49 * 128; idx += 256) {
            int o = idx >> 7, i = idx & 127;
            s_w[idx] = w[o * 256 + ic0 + i];
        }
        __syncthreads();
#pragma unroll 2
        for (int i = 0; i < 128; i += 4) {
            float4 x4 = *reinterpret_cast<const float4*>(xr + ic0 + i);
#pragma unroll
            for (int o = 0; o < 49; o++) {
                const float* wp = &s_w[o * 128 + i];
                acc[o] += x4.x * wp[0] + x4.y * wp[1] + x4.z * wp[2] + x4.w * wp[3];
            }
        }
    }
    float m = -1e30f;
#pragma unroll
    for (int o = 0; o < 49; o++) {
        acc[o] = fmaxf(acc[o] + bias[o], 0.0f);
        m = fmaxf(m, acc[o]);
    }
    float sum = 0.0f;
#pragma unroll
    for (int o = 0; o < 49; o++) {
        acc[o] = expf(acc[o] - m);
        sum += acc[o];
    }
    float inv = 1.0f / sum;
    if (valid) {
        float* k_img = ker + (size_t)img * 49 * NPIX;
#pragma unroll
        for (int o = 0; o < 49; o++)
            k_img[(size_t)o * NPIX + p] = acc[o] * inv;
    }
}

// -------- spatially-variant 7x7 conv (unchanged, passing) -------------------
__global__ __launch_bounds__(256) void svconv_kernel(const float* __restrict__ f,
                              const float* __restrict__ ker,
                              float* __restrict__ out) {
    __shared__ float s_f[8][22][22];
    const int tx = threadIdx.x & 15, ty = threadIdx.x >> 4;
    const int col0 = blockIdx.x * 16, row0 = blockIdx.y * 16;
    const int z = blockIdx.z;
    const int c_base = (z & 3) * 64;
    const int img = z >> 2;

    const int gy = row0 + ty, gx = col0 + tx;
    const bool valid = (gy < 129) && (gx < 129);
    const float* f_img = f   + (size_t)img * 256 * NPIX;
    const float* k_img = ker + (size_t)img * 49  * NPIX;
    float*       o_img = out + (size_t)img * 256 * NPIX;

    float kv[49];
    int pclamp = valid ? gy * W129 + gx : 0;
#pragma unroll
    for (int o = 0; o < 49; o++) kv[o] = k_img[(size_t)o * NPIX + pclamp];

    for (int cc = 0; cc < 64; cc += 8) {
        __syncthreads();
        for (int idx = threadIdx.x; idx < 8 * 22 * 22; idx += 256) {
            int cx = idx % 22;
            int cy = (idx / 22) % 22;
            int ch = idx / 484;
            int gr = row0 - 3 + cy, gc = col0 - 3 + cx;
            float v = 0.0f;
            if ((unsigned)gr < 129u && (unsigned)gc < 129u)
                v = f_img[(size_t)(c_base + cc + ch) * NPIX + gr * W129 + gc];
            s_f[ch][cy][cx] = v;
        }
        __syncthreads();
#pragma unroll 1
        for (int ch = 0; ch < 8; ch++) {
            float acc = 0.0f;
#pragma unroll
            for (int i = 0; i < 7; i++)
#pragma unroll
                for (int j = 0; j < 7; j++)
                    acc += kv[i * 7 + j] * s_f[ch][ty + i][tx + j];
            if (valid)
                o_img[(size_t)(c_base + cc + ch) * NPIX + gy * W129 + gx] = acc;
        }
    }
}

// ========================= launch ============================================
extern "C" void kernel_launch(void* const* d_in, const int* in_sizes, int n_in,
                              void* d_out, int out_size) {
    const float* cur      = (const float*)d_in[0];
    const float* key      = (const float*)d_in[1];
    const float* high     = (const float*)d_in[2];
    const float* w_reduce = (const float*)d_in[3];
    const float* b_reduce = (const float*)d_in[4];
    const float* w_conv2  = (const float*)d_in[5];
    const float* b_conv2  = (const float*)d_in[6];
    const float* w_conv3  = (const float*)d_in[7];
    const float* b_conv3  = (const float*)d_in[8];
    float* out = (float*)d_out;

    float *ups, *ccat, *wtr, *wt2, *yb, *kb;
    cudaGetSymbolAddress((void**)&ups,  g_ups);
    cudaGetSymbolAddress((void**)&ccat, g_ccat);
    cudaGetSymbolAddress((void**)&wtr,  g_wtr);
    cudaGetSymbolAddress((void**)&wt2,  g_wt2);
    cudaGetSymbolAddress((void**)&yb,   g_y);
    cudaGetSymbolAddress((void**)&kb,   g_ker);

    const int SMEM_DYN = 3 * STAGEBYTES;   // 110592 -> 2 CTAs/SM
    cudaFuncSetAttribute(conv_mma_kernel<128, true>,
                         cudaFuncAttributeMaxDynamicSharedMemorySize, SMEM_DYN);
    cudaFuncSetAttribute(conv_mma_kernel<512, false>,
                         cudaFuncAttributeMaxDynamicSharedMemorySize, SMEM_DYN);

    // 1. zero padded NHWC buffers (halos + garbage tail must read 0)
    zero_kernel<<<2048, 256>>>((float4*)ups,  (size_t)4 * PADROWS * 128 / 4,
                               (float4*)ccat, (size_t)2 * PADROWS * 512 / 4);
    // 2. weights -> [rs][oc][ic], tf32
    {
        int t1 = 9 * 256 * 128;
        transpose_w_tf32<<<(t1 + 255) / 256, 256>>>(w_reduce, wtr, 128);
        int t2 = 9 * 256 * 512;
        transpose_w_tf32<<<(t2 + 255) / 256, 256>>>(w_conv2, wt2, 512);
    }
    // 3. bilinear upsample -> NHWC padded, tf32
    {
        dim3 grid(129, 4);
        upsample_nhwc<<<grid, 256>>>(cur, key, ups);
    }
    // 4. conv_reduce: 4 imgs, IC=128 -> ccat (NHWC padded, tf32)
    {
        dim3 grid(MT128, 4, 2);
        conv_mma_kernel<128, true><<<grid, 256, SMEM_DYN>>>(ups, wtr, b_reduce, ccat);
    }
    // 5. conv2: 2 imgs, IC=512 -> y (NHWC, fp32)
    {
        dim3 grid(MT128, 2, 2);
        conv_mma_kernel<512, false><<<grid, 256, SMEM_DYN>>>(ccat, wt2, b_conv2, yb);
    }
    // 6. 1x1 conv + softmax -> kernels
    {
        dim3 grid((NPIX + 255) / 256, 2);
        conv1x1_softmax_nhwc<<<grid, 256>>>(yb, w_conv3, b_conv3, kb);
    }
    // 7. spatially-variant 7x7 conv -> output
    {
        dim3 grid(9, 9, 8);
        svconv_kernel<<<grid, 256>>>(high, kb, out);
    }
}

// round 16
// speedup vs baseline: 1.0625x; 1.0042x over previous
#include <cuda_runtime.h>
#include <cstdint>

#define W129 129
#define NPIX (129*129)
#define PW   131
#define PADROWS 17792
#define MT128 133          // ceil(16899/128) M-tiles of 128

// ---------------- scratch (device globals) ----------------------------------
__device__ float g_ups[4u*PADROWS*128];     // [img][padpos][128] NHWC, tf32 vals
__device__ float g_ccat[2u*PADROWS*512];    // [b][padpos][512]   NHWC, tf32 vals
__device__ float g_wtr[9*256*128];          // [rs][oc][ic] tf32
__device__ float g_wt2[9*256*512];          // [rs][oc][ic] tf32
__device__ float g_y[2u*NPIX*256];          // [img][pix][256] fp32 NHWC
__device__ float g_ker[2*49*NPIX];          // [img][o][pix]

// ========================= helpers ==========================================
__device__ __forceinline__ float tf32r(float x) {
    asm("cvt.rna.tf32.f32 %0, %0;" : "+f"(x));
    return x;
}
__device__ __forceinline__ uint32_t smem_u32(const void* p) {
    uint32_t a;
    asm("{ .reg .u64 t; cvta.to.shared.u64 t, %1; cvt.u32.u64 %0, t; }" : "=r"(a) : "l"(p));
    return a;
}
__device__ __forceinline__ void cp_async16(uint32_t dst, const void* src) {
    asm volatile("cp.async.cg.shared.global [%0], [%1], 16;" :: "r"(dst), "l"(src) : "memory");
}
__device__ __forceinline__ void cp_commit() {
    asm volatile("cp.async.commit_group;" ::: "memory");
}
__device__ __forceinline__ void mma_tf32_16x8x8(float* c, const uint32_t* a, const uint32_t* b) {
    asm volatile(
        "mma.sync.aligned.m16n8k8.row.col.f32.tf32.tf32.f32 "
        "{%0,%1,%2,%3}, {%4,%5,%6,%7}, {%8,%9}, {%0,%1,%2,%3};"
        : "+f"(c[0]), "+f"(c[1]), "+f"(c[2]), "+f"(c[3])
        : "r"(a[0]), "r"(a[1]), "r"(a[2]), "r"(a[3]), "r"(b[0]), "r"(b[1]));
}

// ========================= aux kernels ======================================
// Zero ONLY the halo/garbage regions of the padded NHWC buffers.
// Interior (rows 1..129, cols 1..129) is rewritten deterministically each call
// by upsample_nhwc / conv1 epilogue. Halo: Y==0, Y>=130, X==0, X==130.
__global__ void zero_halo_kernel(float* __restrict__ ups, float* __restrict__ ccat) {
    int idx = blockIdx.x * blockDim.x + threadIdx.x;
    const int total = 6 * PADROWS;             // 4 ups imgs + 2 ccat imgs
    if (idx >= total) return;
    int img = idx / PADROWS;
    int p = idx - img * PADROWS;
    int Y = p / PW, X = p - Y * PW;
    bool halo = (Y == 0) | (Y >= 130) | (X == 0) | (X >= 130);
    if (!halo) return;
    float4 z = make_float4(0.f, 0.f, 0.f, 0.f);
    if (img < 4) {
        float4* d = reinterpret_cast<float4*>(ups + ((size_t)img * PADROWS + p) * 128);
#pragma unroll
        for (int i = 0; i < 32; i++) d[i] = z;
    } else {
        float4* d = reinterpret_cast<float4*>(ccat + ((size_t)(img - 4) * PADROWS + p) * 512);
#pragma unroll
        for (int i = 0; i < 128; i++) d[i] = z;
    }
}

__global__ void transpose_w_tf32(const float* __restrict__ src,
                                 float* __restrict__ dst, int IC) {
    int idx = blockIdx.x * blockDim.x + threadIdx.x;
    int total = 9 * 256 * IC;
    if (idx >= total) return;
    int ic = idx % IC;
    int oc = (idx / IC) % 256;
    int rs = idx / (IC * 256);
    dst[idx] = tf32r(src[((size_t)oc * IC + ic) * 9 + rs]);
}

__global__ __launch_bounds__(256) void upsample_nhwc(const float* __restrict__ cur,
                                                     const float* __restrict__ key,
                                                     float* __restrict__ ups) {
    __shared__ float s[128][2][33];
    __shared__ float s_fx[129];
    __shared__ int   s_x0[129];
    int y = blockIdx.x;          // 0..128
    int img = blockIdx.y;        // 0..3
    int b = img >> 1, frame = img & 1;
    const float* src = (frame ? key : cur) + (size_t)b * 128 * 1089;
    const float scale = 33.0f / 129.0f;
    float sy = fminf(fmaxf((y + 0.5f) * scale - 0.5f, 0.0f), 32.0f);
    int y0 = (int)sy, y1 = min(y0 + 1, 32);
    float fy = sy - (float)y0;
    // per-column tables (computed once per block)
    for (int x = threadIdx.x; x < 129; x += 256) {
        float sx = fminf(fmaxf((x + 0.5f) * scale - 0.5f, 0.0f), 32.0f);
        int x0 = (int)sx;
        float fx = sx - (float)x0;
        if (x0 >= 32) { x0 = 31; fx = 1.0f; }   // keep x1 = x0+1 <= 32
        s_x0[x] = x0;
        s_fx[x] = fx;
    }
    for (int idx = threadIdx.x; idx < 128 * 66; idx += 256) {
        int c = idx / 66, rem = idx % 66;
        int yy = rem / 33, x = rem % 33;
        s[c][yy][x] = src[c * 1089 + (yy ? y1 : y0) * 33 + x];
    }
    __syncthreads();
    float* dst = ups + ((size_t)img * PADROWS + (size_t)(y + 1) * PW + 1) * 128;
    for (int e = threadIdx.x; e < 129 * 128; e += 256) {
        int x = e >> 7, c = e & 127;
        int x0 = s_x0[x];
        float fx = s_fx[x];
        float v0 = s[c][0][x0] + (s[c][0][x0 + 1] - s[c][0][x0]) * fx;
        float v1 = s[c][1][x0] + (s[c][1][x0 + 1] - s[c][1][x0]) * fx;
        dst[(size_t)x * 128 + c] = tf32r(v0 + (v1 - v0) * fy);
    }
}

// ============== warp-MMA tf32 implicit-GEMM 3x3 conv ========================
// CTA: M=128 padded-grid positions x N=128 oc. 8 warps, each 64x32.
// K-chunks of 32 ic per tap; 3-stage cp.async, ONE barrier per chunk:
//   wait_group -> bar (publishes chunk j, frees stage (j-1)%3) -> issue -> mma
#define SK 36
#define STAGEFLOATS (2 * 128 * SK)            // 9216
#define STAGEBYTES  (STAGEFLOATS * 4)         // 36864

template<int IC, bool TO_CCAT>
__global__ __launch_bounds__(256, 2)
void conv_mma_kernel(const float* __restrict__ in,
                     const float* __restrict__ wt,
                     const float* __restrict__ bias,
                     float* __restrict__ outbuf) {
    extern __shared__ float dsm[];

    const int tid = threadIdx.x;
    const int wid = tid >> 5;
    const int lane = tid & 31;
    const int r = lane >> 2;         // 0..7
    const int cth = lane & 3;        // 0..3

    const int q0 = blockIdx.x * 128;
    const int img = blockIdx.y;
    const int ocbase = blockIdx.z * 128;
    const int wm = wid & 1;          // m-half (64)
    const int wn = wid >> 1;         // n-quarter (32)

    const float* in_img = in + (size_t)img * PADROWS * IC;
    const uint32_t smem0 = smem_u32(dsm);

    const int KC = IC / 32;          // ic-chunks per tap
    const int NK = 9 * KC;

    float c[4][4][4];
#pragma unroll
    for (int mt = 0; mt < 4; mt++)
#pragma unroll
        for (int nt = 0; nt < 4; nt++)
#pragma unroll
            for (int v = 0; v < 4; v++) c[mt][nt][v] = 0.0f;

    const int l_row = tid >> 3;      // 0..31
    const int l_k4  = tid & 7;       // float4 index within 32 floats

    // ---- chunk loader ----
    auto issue_chunk = [&](int ch, int buf) {
        int rs = ch / KC, icc = ch % KC;
        int dq = (rs / 3) * PW + (rs % 3);
        int ic0 = icc * 32;
        uint32_t As = smem0 + buf * STAGEBYTES;
        uint32_t Bs = As + 128 * SK * 4;
        const float* gA = in_img + (size_t)(q0 + dq) * IC + ic0;
        const float* gB = wt + ((size_t)rs * 256 + ocbase) * IC + ic0;
#pragma unroll
        for (int i = 0; i < 4; i++) {
            int row = l_row + i * 32;
            cp_async16(As + row * (SK * 4) + l_k4 * 16, gA + (size_t)row * IC + l_k4 * 4);
        }
#pragma unroll
        for (int i = 0; i < 4; i++) {
            int row = l_row + i * 32;
            cp_async16(Bs + row * (SK * 4) + l_k4 * 16, gB + (size_t)row * IC + l_k4 * 4);
        }
        cp_commit();
    };

    issue_chunk(0, 0);
    issue_chunk(1, 1);

    for (int j = 0; j < NK; j++) {
        // chunk j's cp.async group done (each thread waits its own groups)
        if (j < NK - 1) asm volatile("cp.async.wait_group 1;" ::: "memory");
        else            asm volatile("cp.async.wait_group 0;" ::: "memory");
        // ONE barrier: publishes chunk j to all warps AND certifies that all
        // warps finished reading stage (j-1)%3 (== (j+2)%3), so it can be refilled.
        __syncthreads();
        if (j + 2 < NK) issue_chunk(j + 2, (j + 2) % 3);

        const float* sAf = dsm + (j % 3) * STAGEFLOATS;
        const float* sBf = sAf + 128 * SK;
        const float* apb = sAf + (wm * 64 + r) * SK + cth;
        const float* bpb = sBf + (wn * 32 + r) * SK + cth;
#pragma unroll
        for (int ks = 0; ks < 4; ks++) {
            int k0 = ks * 8;
            uint32_t a[4][4], b[4][2];
#pragma unroll
            for (int mt = 0; mt < 4; mt++) {
                const float* ap = apb + mt * 16 * SK + k0;
                a[mt][0] = __float_as_uint(ap[0]);
                a[mt][1] = __float_as_uint(ap[8 * SK]);
                a[mt][2] = __float_as_uint(ap[4]);
                a[mt][3] = __float_as_uint(ap[8 * SK + 4]);
            }
#pragma unroll
            for (int nt = 0; nt < 4; nt++) {
                const float* bp = bpb + nt * 8 * SK + k0;
                b[nt][0] = __float_as_uint(bp[0]);
                b[nt][1] = __float_as_uint(bp[4]);
            }
#pragma unroll
            for (int mt = 0; mt < 4; mt++)
#pragma unroll
                for (int nt = 0; nt < 4; nt++)
                    mma_tf32_16x8x8(c[mt][nt], a[mt], b[nt]);
        }
    }

    // ---- epilogue: bias + relu, scatter to NHWC ----
#pragma unroll
    for (int nt = 0; nt < 4; nt++) {
        int nglob = ocbase + wn * 32 + nt * 8 + cth * 2;
        float b0 = __ldg(bias + nglob);
        float b1 = __ldg(bias + nglob + 1);
#pragma unroll
        for (int mt = 0; mt < 4; mt++) {
#pragma unroll
            for (int half = 0; half < 2; half++) {
                int q = q0 + wm * 64 + mt * 16 + r + half * 8;
                int Y = q / PW, X = q - Y * PW;
                if (X < 129 && Y < 129) {
                    float v0 = fmaxf(c[mt][nt][half * 2 + 0] + b0, 0.0f);
                    float v1 = fmaxf(c[mt][nt][half * 2 + 1] + b1, 0.0f);
                    float* dst;
                    if (TO_CCAT) {
                        v0 = tf32r(v0); v1 = tf32r(v1);
                        dst = outbuf + ((size_t)(img >> 1) * PADROWS
                              + (size_t)(Y + 1) * PW + (X + 1)) * 512
                              + (img & 1) * 256 + nglob;
                    } else {
                        dst = outbuf + ((size_t)img * NPIX + (size_t)Y * W129 + X) * 256 + nglob;
                    }
                    *reinterpret_cast<float2*>(dst) = make_float2(v0, v1);
                }
            }
        }
    }
}

// -------- 1x1 conv (NHWC input) + bias + relu + softmax ---------------------
__global__ __launch_bounds__(256) void conv1x1_softmax_nhwc(
        const float* __restrict__ yb, const float* __restrict__ w,
        const float* __restrict__ bias, float* __restrict__ ker) {
    __shared__ float s_w[49 * 128];
    const int img = blockIdx.y;
    int p = blockIdx.x * 256 + threadIdx.x;
    const bool valid = p < NPIX;
    int pc = valid ? p : NPIX - 1;
    const float* xr = yb + ((size_t)img * NPIX + pc) * 256;

    float acc[49];
#pragma unroll
    for (int o = 0; o < 49; o++) acc[o] = 0.0f;

    for (int ic0 = 0; ic0 < 256; ic0 += 128) {
        __syncthreads();
        for (int idx = threadIdx.x; idx < 49 * 128; idx += 256) {
            int o = idx >> 7, i = idx & 127;
            s_w[idx] = w[o * 256 + ic0 + i];
        }
        __syncthreads();
#pragma unroll 2
        for (int i = 0; i < 128; i += 4) {
            float4 x4 = *reinterpret_cast<const float4*>(xr + ic0 + i);
#pragma unroll
            for (int o = 0; o < 49; o++) {
                const float* wp = &s_w[o * 128 + i];
                acc[o] += x4.x * wp[0] + x4.y * wp[1] + x4.z * wp[2] + x4.w * wp[3];
            }
        }
    }
    float m = -1e30f;
#pragma unroll
    for (int o = 0; o < 49; o++) {
        acc[o] = fmaxf(acc[o] + bias[o], 0.0f);
        m = fmaxf(m, acc[o]);
    }
    float sum = 0.0f;
#pragma unroll
    for (int o = 0; o < 49; o++) {
        acc[o] = expf(acc[o] - m);
        sum += acc[o];
    }
    float inv = 1.0f / sum;
    if (valid) {
        float* k_img = ker + (size_t)img * 49 * NPIX;
#pragma unroll
        for (int o = 0; o < 49; o++)
            k_img[(size_t)o * NPIX + p] = acc[o] * inv;
    }
}

// -------- spatially-variant 7x7 conv (unchanged, passing) -------------------
__global__ __launch_bounds__(256) void svconv_kernel(const float* __restrict__ f,
                              const float* __restrict__ ker,
                              float* __restrict__ out) {
    __shared__ float s_f[8][22][22];
    const int tx = threadIdx.x & 15, ty = threadIdx.x >> 4;
    const int col0 = blockIdx.x * 16, row0 = blockIdx.y * 16;
    const int z = blockIdx.z;
    const int c_base = (z & 3) * 64;
    const int img = z >> 2;

    const int gy = row0 + ty, gx = col0 + tx;
    const bool valid = (gy < 129) && (gx < 129);
    const float* f_img = f   + (size_t)img * 256 * NPIX;
    const float* k_img = ker + (size_t)img * 49  * NPIX;
    float*       o_img = out + (size_t)img * 256 * NPIX;

    float kv[49];
    int pclamp = valid ? gy * W129 + gx : 0;
#pragma unroll
    for (int o = 0; o < 49; o++) kv[o] = k_img[(size_t)o * NPIX + pclamp];

    for (int cc = 0; cc < 64; cc += 8) {
        __syncthreads();
        for (int idx = threadIdx.x; idx < 8 * 22 * 22; idx += 256) {
            int cx = idx % 22;
            int cy = (idx / 22) % 22;
            int ch = idx / 484;
            int gr = row0 - 3 + cy, gc = col0 - 3 + cx;
            float v = 0.0f;
            if ((unsigned)gr < 129u && (unsigned)gc < 129u)
                v = f_img[(size_t)(c_base + cc + ch) * NPIX + gr * W129 + gc];
            s_f[ch][cy][cx] = v;
        }
        __syncthreads();
#pragma unroll 1
        for (int ch = 0; ch < 8; ch++) {
            float acc = 0.0f;
#pragma unroll
            for (int i = 0; i < 7; i++)
#pragma unroll
                for (int j = 0; j < 7; j++)
                    acc += kv[i * 7 + j] * s_f[ch][ty + i][tx + j];
            if (valid)
                o_img[(size_t)(c_base + cc + ch) * NPIX + gy * W129 + gx] = acc;
        }
    }
}

// ========================= launch ============================================
extern "C" void kernel_launch(void* const* d_in, const int* in_sizes, int n_in,
                              void* d_out, int out_size) {
    const float* cur      = (const float*)d_in[0];
    const float* key      = (const float*)d_in[1];
    const float* high     = (const float*)d_in[2];
    const float* w_reduce = (const float*)d_in[3];
    const float* b_reduce = (const float*)d_in[4];
    const float* w_conv2  = (const float*)d_in[5];
    const float* b_conv2  = (const float*)d_in[6];
    const float* w_conv3  = (const float*)d_in[7];
    const float* b_conv3  = (const float*)d_in[8];
    float* out = (float*)d_out;

    float *ups, *ccat, *wtr, *wt2, *yb, *kb;
    cudaGetSymbolAddress((void**)&ups,  g_ups);
    cudaGetSymbolAddress((void**)&ccat, g_ccat);
    cudaGetSymbolAddress((void**)&wtr,  g_wtr);
    cudaGetSymbolAddress((void**)&wt2,  g_wt2);
    cudaGetSymbolAddress((void**)&yb,   g_y);
    cudaGetSymbolAddress((void**)&kb,   g_ker);

    const int SMEM_DYN = 3 * STAGEBYTES;   // 110592 -> 2 CTAs/SM
    cudaFuncSetAttribute(conv_mma_kernel<128, true>,
                         cudaFuncAttributeMaxDynamicSharedMemorySize, SMEM_DYN);
    cudaFuncSetAttribute(conv_mma_kernel<512, false>,
                         cudaFuncAttributeMaxDynamicSharedMemorySize, SMEM_DYN);

    // 1. zero ONLY halo regions (interiors rewritten deterministically below)
    {
        int total = 6 * PADROWS;
        zero_halo_kernel<<<(total + 255) / 256, 256>>>(ups, ccat);
    }
    // 2. weights -> [rs][oc][ic], tf32
    {
        int t1 = 9 * 256 * 128;
        transpose_w_tf32<<<(t1 + 255) / 256, 256>>>(w_reduce, wtr, 128);
        int t2 = 9 * 256 * 512;
        transpose_w_tf32<<<(t2 + 255) / 256, 256>>>(w_conv2, wt2, 512);
    }
    // 3. bilinear upsample -> NHWC padded, tf32
    {
        dim3 grid(129, 4);
        upsample_nhwc<<<grid, 256>>>(cur, key, ups);
    }
    // 4. conv_reduce: 4 imgs, IC=128 -> ccat (NHWC padded, tf32)
    {
        dim3 grid(MT128, 4, 2);
        conv_mma_kernel<128, true><<<grid, 256, SMEM_DYN>>>(ups, wtr, b_reduce, ccat);
    }
    // 5. conv2: 2 imgs, IC=512 -> y (NHWC, fp32)
    {
        dim3 grid(MT128, 2, 2);
        conv_mma_kernel<512, false><<<grid, 256, SMEM_DYN>>>(ccat, wt2, b_conv2, yb);
    }
    // 6. 1x1 conv + softmax -> kernels
    {
        dim3 grid((NPIX + 255) / 256, 2);
        conv1x1_softmax_nhwc<<<grid, 256>>>(yb, w_conv3, b_conv3, kb);
    }
    // 7. spatially-variant 7x7 conv -> output
    {
        dim3 grid(9, 9, 8);
        svconv_kernel<<<grid, 256>>>(high, kb, out);
    }
}